// round 8
// baseline (speedup 1.0000x reference)
#include <cuda_runtime.h>
#include <math.h>

#define NB   8
#define C    128
#define H    56
#define W    56
#define O    64
#define NC   2
#define KS   5
#define P    25
#define P2   50           // NC * P
#define HW   (H * W)      // 3136
#define PIX  (NB * HW)    // 25088
#define CP   (C * P)      // 3200
#define PPB  ((PIX + 147) / 148)   // 170 pixels per proj block

typedef unsigned long long u64;

// Scratch (allocation-free rule: __device__ globals)
__device__ __align__(16) float g_V[P2 * C];  // folded weights V[p2][c]
__device__ float g_const[NC];                // per-class constant
__device__ float g_Y[NB * P * HW * 2];       // Y[n][p][hw][{class0,class1}]

__device__ __forceinline__ void fma2(u64& d, u64 a, u64 b) {
    asm("fma.rn.f32x2 %0, %1, %2, %0;" : "+l"(d) : "l"(a), "l"(b));
}
__device__ __forceinline__ u64 pack2(float lo, float hi) {
    u64 r;
    asm("mov.b64 %0, {%1, %2};" : "=l"(r) : "f"(lo), "f"(hi));
    return r;
}
__device__ __forceinline__ float hadd2(u64 v) {
    float lo, hi;
    asm("mov.b64 {%0, %1}, %2;" : "=f"(lo), "=f"(hi) : "l"(v));
    return lo + hi;
}

// ---------------------------------------------------------------------------
// Kernel 1: V = Wlin(2x64) @ Wt(64x3200).
// 100 blocks x 256 threads. Warp w reduces o in [8w, 8w+8) for 32 coalesced
// j's; shared reduce across the 8 warps. 25600 threads, 8 LDGs each -> MLP
// hides DRAM latency (the R5 version had 3200 threads @ 64 serialized LDGs).
// ---------------------------------------------------------------------------
__global__ void __launch_bounds__(256) prep_kernel(const float* __restrict__ Wt,
                                                   const float* __restrict__ bias,
                                                   const float* __restrict__ Wlin,
                                                   const float* __restrict__ blin) {
    __shared__ float red0[8][32];
    __shared__ float red1[8][32];
    int w = threadIdx.x >> 5;
    int l = threadIdx.x & 31;
    int j = blockIdx.x * 32 + l;          // 0..3199 = c*25 + p

    float s0 = 0.f, s1 = 0.f;
    #pragma unroll
    for (int oo = 0; oo < 8; oo++) {
        int o = w * 8 + oo;
        float wt = Wt[o * CP + j];        // 8 independent coalesced LDGs
        s0 = fmaf(__ldg(&Wlin[o]),     wt, s0);
        s1 = fmaf(__ldg(&Wlin[O + o]), wt, s1);
    }
    red0[w][l] = s0;
    red1[w][l] = s1;
    __syncthreads();

    if (w == 0) {
        float t0 = 0.f, t1 = 0.f;
        #pragma unroll
        for (int k = 0; k < 8; k++) { t0 += red0[k][l]; t1 += red1[k][l]; }
        int c = j / P, p = j % P;
        g_V[p * C + c]       = t0;        // p2 = p       (class 0)
        g_V[(P + p) * C + c] = t1;        // p2 = 25 + p  (class 1)
    }

    if (blockIdx.x == 0 && threadIdx.x < NC) {
        float s = blin[threadIdx.x];
        #pragma unroll
        for (int o = 0; o < O; o++) s += bias[o] * Wlin[threadIdx.x * O + o];
        g_const[threadIdx.x] = s;
    }
}

// ---------------------------------------------------------------------------
// Kernel 2: pointwise projection, packed f32x2 over channel pairs.
// Grid = 148 blocks (one per SM), each owning a contiguous 170-pixel chunk:
// eliminates the 2-blocks-on-48-SMs tail of the 196-block launch.
// ---------------------------------------------------------------------------
__global__ void __launch_bounds__(128) proj_kernel(const float* __restrict__ x) {
    __shared__ __align__(16) float sV[P2 * C];        // 25.6 KB
    for (int i = threadIdx.x; i < P2 * C / 4; i += blockDim.x)
        reinterpret_cast<float4*>(sV)[i] = reinterpret_cast<const float4*>(g_V)[i];
    __syncthreads();

    const ulonglong2* sV2 = reinterpret_cast<const ulonglong2*>(sV);
    int base = blockIdx.x * PPB;
    int cnt  = min(PPB, PIX - base);

    for (int i = threadIdx.x; i < cnt; i += 128) {
        int pix = base + i;
        int n  = pix / HW;
        int hw = pix % HW;
        const float* xb = x + (size_t)n * C * HW + hw;

        u64 acc[P2];
        #pragma unroll
        for (int p = 0; p < P2; p++) acc[p] = 0ull;

        #pragma unroll 2
        for (int c4 = 0; c4 < C / 4; c4++) {
            float x0 = xb[(c4 * 4 + 0) * HW];
            float x1 = xb[(c4 * 4 + 1) * HW];
            float x2 = xb[(c4 * 4 + 2) * HW];
            float x3 = xb[(c4 * 4 + 3) * HW];
            u64 xp01 = pack2(x0, x1);
            u64 xp23 = pack2(x2, x3);
            #pragma unroll
            for (int p = 0; p < P2; p++) {
                ulonglong2 wv = sV2[p * (C / 4) + c4];  // LDS.128 broadcast
                fma2(acc[p], wv.x, xp01);
                fma2(acc[p], wv.y, xp23);
            }
        }

        // horizontal add + class-interleaved store: Y[n][p][hw][2]
        float2* yb = reinterpret_cast<float2*>(g_Y) + (size_t)n * P * HW + hw;
        #pragma unroll
        for (int p = 0; p < P; p++) {
            float2 v;
            v.x = hadd2(acc[p]);
            v.y = hadd2(acc[P + p]);
            yb[p * HW] = v;
        }
    }
}

// ---------------------------------------------------------------------------
// Kernel 3: 5x5 spatial gather (one LDG.64 per tap) + drift/exp epilogue.
// ---------------------------------------------------------------------------
__global__ void __launch_bounds__(128) final_kernel(float* __restrict__ out) {
    int pix = blockIdx.x * blockDim.x + threadIdx.x;
    if (pix >= PIX) return;
    int n  = pix / HW;
    int hw = pix % HW;
    int h  = hw / W;
    int w  = hw % W;

    const float2* yb = reinterpret_cast<const float2*>(g_Y) + (size_t)n * P * HW;
    float c0 = g_const[0], c1 = g_const[1];

    float sum0 = 0.f, sum1 = 0.f;
    float as0 = 0.f, as1 = 0.f;
    float ys0 = 0.f, ys1 = 0.f;
    float xs0 = 0.f, xs1 = 0.f;

    #pragma unroll
    for (int i = 0; i < KS; i++) {
        int hh = h + i - 2;
        bool hin = (hh >= 0) && (hh < H);
        #pragma unroll
        for (int j = 0; j < KS; j++) {
            int ww = w + j - 2;
            bool in = hin && (ww >= 0) && (ww < W);
            int p = i * KS + j;
            float2 v = make_float2(0.f, 0.f);
            if (in) v = yb[p * HW + hh * W + ww];
            float m0 = v.x + c0, m1 = v.y + c1;
            float a0 = fabsf(m0), a1 = fabsf(m1);
            float yo = (float)(i - 2), xo = (float)(j - 2);
            sum0 += m0;      sum1 += m1;
            as0  += a0;      as1  += a1;
            ys0  = fmaf(a0, yo, ys0);  ys1 = fmaf(a1, yo, ys1);
            xs0  = fmaf(a0, xo, xs0);  xs1 = fmaf(a1, xo, xs1);
        }
    }

    float yd0 = ys0 / as0, xd0 = xs0 / as0;
    float yd1 = ys1 / as1, xd1 = xs1 / as1;
    float d0 = sqrtf(fmaf(xd0, xd0, yd0 * yd0));
    float d1 = sqrtf(fmaf(xd1, xd1, yd1 * yd1));
    out[pix * 2 + 0] = sum0 * expf(-0.5f * d0);
    out[pix * 2 + 1] = sum1 * expf(-0.5f * d1);
}

// ---------------------------------------------------------------------------
extern "C" void kernel_launch(void* const* d_in, const int* in_sizes, int n_in,
                              void* d_out, int out_size) {
    const float* x    = (const float*)d_in[0];  // (8,128,56,56)
    const float* Wt   = (const float*)d_in[1];  // (64,128,5,5)
    const float* bias = (const float*)d_in[2];  // (64,)
    const float* Wlin = (const float*)d_in[3];  // (2,64)
    const float* blin = (const float*)d_in[4];  // (2,)
    float* out = (float*)d_out;                 // (8,56,56,2)

    prep_kernel<<<CP / 32, 256>>>(Wt, bias, Wlin, blin);   // 100 blocks
    proj_kernel<<<148, 128>>>(x);                          // one block per SM
    final_kernel<<<(PIX + 127) / 128, 128>>>(out);         // 196 blocks
}

// round 9
// speedup vs baseline: 1.2223x; 1.2223x over previous
#include <cuda_runtime.h>
#include <math.h>

#define NB   8
#define C    128
#define H    56
#define W    56
#define O    64
#define NC   2
#define KS   5
#define P    25
#define P2   50           // NC * P
#define HW   (H * W)      // 3136
#define PIX  (NB * HW)    // 25088
#define CP   (C * P)      // 3200

typedef unsigned long long u64;

// Scratch (allocation-free rule: __device__ globals)
__device__ __align__(16) float g_V[P2 * C];  // folded weights V[p2][c]
__device__ float g_const[NC];                // per-class constant
__device__ float g_Y[NB * P * HW * 2];       // Y[n][p][hw][{class0,class1}]

__device__ __forceinline__ void fma2(u64& d, u64 a, u64 b) {
    asm("fma.rn.f32x2 %0, %1, %2, %0;" : "+l"(d) : "l"(a), "l"(b));
}
__device__ __forceinline__ u64 pack2(float lo, float hi) {
    u64 r;
    asm("mov.b64 %0, {%1, %2};" : "=l"(r) : "f"(lo), "f"(hi));
    return r;
}
__device__ __forceinline__ float hadd2(u64 v) {
    float lo, hi;
    asm("mov.b64 {%0, %1}, %2;" : "=f"(lo), "=f"(hi) : "l"(v));
    return lo + hi;
}

// ---------------------------------------------------------------------------
// Kernel 1: V = Wlin(2x64) @ Wt(64x3200). Warp w reduces 8 o's for 32
// coalesced j's; shared reduce across the 8 warps. (Best measured prep.)
// ---------------------------------------------------------------------------
__global__ void __launch_bounds__(256) prep_kernel(const float* __restrict__ Wt,
                                                   const float* __restrict__ bias,
                                                   const float* __restrict__ Wlin,
                                                   const float* __restrict__ blin) {
    __shared__ float red0[8][32];
    __shared__ float red1[8][32];
    int w = threadIdx.x >> 5;
    int l = threadIdx.x & 31;
    int j = blockIdx.x * 32 + l;          // 0..3199 = c*25 + p

    float s0 = 0.f, s1 = 0.f;
    #pragma unroll
    for (int oo = 0; oo < 8; oo++) {
        int o = w * 8 + oo;
        float wt = Wt[o * CP + j];        // 8 independent coalesced LDGs
        s0 = fmaf(__ldg(&Wlin[o]),     wt, s0);
        s1 = fmaf(__ldg(&Wlin[O + o]), wt, s1);
    }
    red0[w][l] = s0;
    red1[w][l] = s1;
    __syncthreads();

    if (w == 0) {
        float t0 = 0.f, t1 = 0.f;
        #pragma unroll
        for (int k = 0; k < 8; k++) { t0 += red0[k][l]; t1 += red1[k][l]; }
        int c = j / P, p = j % P;
        g_V[p * C + c]       = t0;        // p2 = p       (class 0)
        g_V[(P + p) * C + c] = t1;        // p2 = 25 + p  (class 1)
    }

    if (blockIdx.x == 0 && threadIdx.x < NC) {
        float s = blin[threadIdx.x];
        #pragma unroll
        for (int o = 0; o < O; o++) s += bias[o] * Wlin[threadIdx.x * O + o];
        g_const[threadIdx.x] = s;
    }
}

// ---------------------------------------------------------------------------
// Kernel 2: projection, class-split. Thread = (pixel, class): 25 f32x2
// accumulators over 128 channels. 2x the warps of the pixel-per-thread
// version (latency hiding), half the registers, zero reduction overhead.
// 196 blocks x 256 threads = 50176 threads (exact).
// ---------------------------------------------------------------------------
__global__ void __launch_bounds__(256) proj_kernel(const float* __restrict__ x) {
    __shared__ __align__(16) float sV[P2 * C];        // 25.6 KB
    for (int i = threadIdx.x; i < P2 * C / 4; i += 256)
        reinterpret_cast<float4*>(sV)[i] = reinterpret_cast<const float4*>(g_V)[i];
    __syncthreads();

    int tid = threadIdx.x;
    int pix = blockIdx.x * 128 + (tid >> 1);          // < PIX by construction
    int k   = tid & 1;                                // class
    int n   = pix / HW;
    int hw  = pix % HW;
    const float* xb = x + (size_t)n * C * HW + hw;

    const ulonglong2* sVk = reinterpret_cast<const ulonglong2*>(sV)
                          + (size_t)k * P * (C / 4);  // this class's 25 rows

    u64 acc[P];
    #pragma unroll
    for (int p = 0; p < P; p++) acc[p] = 0ull;

    #pragma unroll 4
    for (int c4 = 0; c4 < C / 4; c4++) {
        float x0 = xb[(c4 * 4 + 0) * HW];
        float x1 = xb[(c4 * 4 + 1) * HW];
        float x2 = xb[(c4 * 4 + 2) * HW];
        float x3 = xb[(c4 * 4 + 3) * HW];
        u64 xp01 = pack2(x0, x1);
        u64 xp23 = pack2(x2, x3);
        #pragma unroll
        for (int p = 0; p < P; p++) {
            ulonglong2 wv = sVk[p * (C / 4) + c4];    // LDS.128, 2 addrs/warp
            fma2(acc[p], wv.x, xp01);
            fma2(acc[p], wv.y, xp23);
        }
    }

    // Store Y[n][p][hw][k]; lane parity = k -> consecutive 4B -> coalesced.
    float* yb = g_Y + (((size_t)n * P) * HW + hw) * 2 + k;
    #pragma unroll
    for (int p = 0; p < P; p++)
        yb[(size_t)p * HW * 2] = hadd2(acc[p]);
}

// ---------------------------------------------------------------------------
// Kernel 3: 5x5 spatial gather (one LDG.64 per tap) + drift/exp epilogue.
// ---------------------------------------------------------------------------
__global__ void __launch_bounds__(128) final_kernel(float* __restrict__ out) {
    int pix = blockIdx.x * blockDim.x + threadIdx.x;
    if (pix >= PIX) return;
    int n  = pix / HW;
    int hw = pix % HW;
    int h  = hw / W;
    int w  = hw % W;

    const float2* yb = reinterpret_cast<const float2*>(g_Y) + (size_t)n * P * HW;
    float c0 = g_const[0], c1 = g_const[1];

    float sum0 = 0.f, sum1 = 0.f;
    float as0 = 0.f, as1 = 0.f;
    float ys0 = 0.f, ys1 = 0.f;
    float xs0 = 0.f, xs1 = 0.f;

    #pragma unroll
    for (int i = 0; i < KS; i++) {
        int hh = h + i - 2;
        bool hin = (hh >= 0) && (hh < H);
        #pragma unroll
        for (int j = 0; j < KS; j++) {
            int ww = w + j - 2;
            bool in = hin && (ww >= 0) && (ww < W);
            int p = i * KS + j;
            float2 v = make_float2(0.f, 0.f);
            if (in) v = yb[p * HW + hh * W + ww];
            float m0 = v.x + c0, m1 = v.y + c1;
            float a0 = fabsf(m0), a1 = fabsf(m1);
            float yo = (float)(i - 2), xo = (float)(j - 2);
            sum0 += m0;      sum1 += m1;
            as0  += a0;      as1  += a1;
            ys0  = fmaf(a0, yo, ys0);  ys1 = fmaf(a1, yo, ys1);
            xs0  = fmaf(a0, xo, xs0);  xs1 = fmaf(a1, xo, xs1);
        }
    }

    float yd0 = ys0 / as0, xd0 = xs0 / as0;
    float yd1 = ys1 / as1, xd1 = xs1 / as1;
    float d0 = sqrtf(fmaf(xd0, xd0, yd0 * yd0));
    float d1 = sqrtf(fmaf(xd1, xd1, yd1 * yd1));
    out[pix * 2 + 0] = sum0 * expf(-0.5f * d0);
    out[pix * 2 + 1] = sum1 * expf(-0.5f * d1);
}

// ---------------------------------------------------------------------------
extern "C" void kernel_launch(void* const* d_in, const int* in_sizes, int n_in,
                              void* d_out, int out_size) {
    const float* x    = (const float*)d_in[0];  // (8,128,56,56)
    const float* Wt   = (const float*)d_in[1];  // (64,128,5,5)
    const float* bias = (const float*)d_in[2];  // (64,)
    const float* Wlin = (const float*)d_in[3];  // (2,64)
    const float* blin = (const float*)d_in[4];  // (2,)
    float* out = (float*)d_out;                 // (8,56,56,2)

    prep_kernel<<<CP / 32, 256>>>(Wt, bias, Wlin, blin);   // 100 blocks
    proj_kernel<<<PIX / 128, 256>>>(x);                    // 196 blocks, exact
    final_kernel<<<(PIX + 127) / 128, 128>>>(out);         // 196 blocks
}

// round 12
// speedup vs baseline: 1.5433x; 1.2626x over previous
#include <cuda_runtime.h>
#include <math.h>

#define NB   8
#define C    128
#define H    56
#define W    56
#define O    64
#define NC   2
#define KS   5
#define P    25
#define P2   50           // NC * P
#define HW   (H * W)      // 3136
#define PIX  (NB * HW)    // 25088
#define CP   (C * P)      // 3200

typedef unsigned long long u64;

// Scratch (allocation-free rule: __device__ globals)
__device__ __align__(16) float g_V[P2 * C];  // folded weights V[k*P+p][c]
__device__ float g_const[NC];                // per-class constant
__device__ float g_Y[NB * P * HW * 2];       // Y[n][p][hw][{class0,class1}]

__device__ __forceinline__ void fma2(u64& d, u64 a, u64 b) {
    asm("fma.rn.f32x2 %0, %1, %2, %0;" : "+l"(d) : "l"(a), "l"(b));
}
__device__ __forceinline__ u64 pack2(float lo, float hi) {
    u64 r;
    asm("mov.b64 %0, {%1, %2};" : "=l"(r) : "f"(lo), "f"(hi));
    return r;
}
__device__ __forceinline__ float hadd2(u64 v) {
    float lo, hi;
    asm("mov.b64 {%0, %1}, %2;" : "=f"(lo), "=f"(hi) : "l"(v));
    return lo + hi;
}

// ---------------------------------------------------------------------------
// Kernel 1: V = Wlin(2x64) @ Wt(64x3200). o split across 16 warps (4 o's
// each, 4 independent coalesced LDGs/thread), shared reduce. 1600 warps.
// ---------------------------------------------------------------------------
__global__ void __launch_bounds__(512) prep_kernel(const float* __restrict__ Wt,
                                                   const float* __restrict__ bias,
                                                   const float* __restrict__ Wlin,
                                                   const float* __restrict__ blin) {
    __shared__ float red0[16][32];
    __shared__ float red1[16][32];
    int w = threadIdx.x >> 5;
    int l = threadIdx.x & 31;
    int j = blockIdx.x * 32 + l;          // 0..3199 = c*25 + p

    float s0 = 0.f, s1 = 0.f;
    #pragma unroll
    for (int oo = 0; oo < 4; oo++) {
        int o = w * 4 + oo;
        float wt = Wt[o * CP + j];        // 4 independent coalesced LDGs
        s0 = fmaf(__ldg(&Wlin[o]),     wt, s0);
        s1 = fmaf(__ldg(&Wlin[O + o]), wt, s1);
    }
    red0[w][l] = s0;
    red1[w][l] = s1;
    __syncthreads();

    if (w == 0) {
        float t0 = 0.f, t1 = 0.f;
        #pragma unroll
        for (int k = 0; k < 16; k++) { t0 += red0[k][l]; t1 += red1[k][l]; }
        int c = j / P, p = j % P;
        g_V[p * C + c]       = t0;        // class 0 rows
        g_V[(P + p) * C + c] = t1;        // class 1 rows
    }

    if (blockIdx.x == 0 && threadIdx.x < NC) {
        float s = blin[threadIdx.x];
        #pragma unroll
        for (int o = 0; o < O; o++) s += bias[o] * Wlin[threadIdx.x * O + o];
        g_const[threadIdx.x] = s;
    }
}

// ---------------------------------------------------------------------------
// Kernel 2: projection. Thread = (pixel-pair, class); class per warp-group so
// the weight LDG.128 is warp-uniform (L1-resident, 1 wavefront) and x LDGs
// are 128B-coalesced. 2 pixels/thread: each weight load feeds 4 FMA2.
// NO shared memory for V — this removes the smem-crossbar wall (~17us).
// 98 blocks x 256 threads, 256 pixels/block, exact.
// ---------------------------------------------------------------------------
__global__ void __launch_bounds__(256, 1) proj_kernel(const float* __restrict__ x) {
    int tid  = threadIdx.x;
    int k    = tid >> 7;                  // warps 0-3: class 0, warps 4-7: class 1
    int slot = tid & 127;
    int pix0 = blockIdx.x * 256 + slot;
    int pix1 = pix0 + 128;

    int n0 = pix0 / HW, hw0 = pix0 % HW;
    int n1 = pix1 / HW, hw1 = pix1 % HW;
    const float* xa = x + (size_t)n0 * C * HW + hw0;
    const float* xb = x + (size_t)n1 * C * HW + hw1;

    const ulonglong2* __restrict__ Vk =
        reinterpret_cast<const ulonglong2*>(g_V) + (size_t)k * P * (C / 4);

    u64 accA[P], accB[P];
    #pragma unroll
    for (int p = 0; p < P; p++) { accA[p] = 0ull; accB[p] = 0ull; }

    #pragma unroll 2
    for (int c4 = 0; c4 < C / 4; c4++) {
        float a0 = xa[(c4 * 4 + 0) * HW];
        float a1 = xa[(c4 * 4 + 1) * HW];
        float a2 = xa[(c4 * 4 + 2) * HW];
        float a3 = xa[(c4 * 4 + 3) * HW];
        float b0 = xb[(c4 * 4 + 0) * HW];
        float b1 = xb[(c4 * 4 + 1) * HW];
        float b2 = xb[(c4 * 4 + 2) * HW];
        float b3 = xb[(c4 * 4 + 3) * HW];
        u64 ap01 = pack2(a0, a1), ap23 = pack2(a2, a3);
        u64 bp01 = pack2(b0, b1), bp23 = pack2(b2, b3);
        #pragma unroll
        for (int p = 0; p < P; p++) {
            ulonglong2 wv = Vk[p * (C / 4) + c4];   // uniform LDG.128, L1-hit
            fma2(accA[p], wv.x, ap01);
            fma2(accA[p], wv.y, ap23);
            fma2(accB[p], wv.x, bp01);
            fma2(accB[p], wv.y, bp23);
        }
    }

    // Y[n][p][hw][k]
    float* ya = g_Y + ((size_t)n0 * P * HW + hw0) * 2 + k;
    float* yb = g_Y + ((size_t)n1 * P * HW + hw1) * 2 + k;
    #pragma unroll
    for (int p = 0; p < P; p++) {
        ya[(size_t)p * HW * 2] = hadd2(accA[p]);
        yb[(size_t)p * HW * 2] = hadd2(accB[p]);
    }
}

// ---------------------------------------------------------------------------
// Kernel 3: 5x5 spatial gather (one LDG.64 per tap) + drift/exp epilogue.
// ---------------------------------------------------------------------------
__global__ void __launch_bounds__(128) final_kernel(float* __restrict__ out) {
    int pix = blockIdx.x * blockDim.x + threadIdx.x;
    if (pix >= PIX) return;
    int n  = pix / HW;
    int hw = pix % HW;
    int h  = hw / W;
    int w  = hw % W;

    const float2* yb = reinterpret_cast<const float2*>(g_Y) + (size_t)n * P * HW;
    float c0 = g_const[0], c1 = g_const[1];

    float sum0 = 0.f, sum1 = 0.f;
    float as0 = 0.f, as1 = 0.f;
    float ys0 = 0.f, ys1 = 0.f;
    float xs0 = 0.f, xs1 = 0.f;

    #pragma unroll
    for (int i = 0; i < KS; i++) {
        int hh = h + i - 2;
        bool hin = (hh >= 0) && (hh < H);
        #pragma unroll
        for (int j = 0; j < KS; j++) {
            int ww = w + j - 2;
            bool in = hin && (ww >= 0) && (ww < W);
            int p = i * KS + j;
            float2 v = make_float2(0.f, 0.f);
            if (in) v = yb[p * HW + hh * W + ww];
            float m0 = v.x + c0, m1 = v.y + c1;
            float a0 = fabsf(m0), a1 = fabsf(m1);
            float yo = (float)(i - 2), xo = (float)(j - 2);
            sum0 += m0;      sum1 += m1;
            as0  += a0;      as1  += a1;
            ys0  = fmaf(a0, yo, ys0);  ys1 = fmaf(a1, yo, ys1);
            xs0  = fmaf(a0, xo, xs0);  xs1 = fmaf(a1, xo, xs1);
        }
    }

    float yd0 = ys0 / as0, xd0 = xs0 / as0;
    float yd1 = ys1 / as1, xd1 = xs1 / as1;
    float d0 = sqrtf(fmaf(xd0, xd0, yd0 * yd0));
    float d1 = sqrtf(fmaf(xd1, xd1, yd1 * yd1));
    out[pix * 2 + 0] = sum0 * expf(-0.5f * d0);
    out[pix * 2 + 1] = sum1 * expf(-0.5f * d1);
}

// ---------------------------------------------------------------------------
extern "C" void kernel_launch(void* const* d_in, const int* in_sizes, int n_in,
                              void* d_out, int out_size) {
    const float* x    = (const float*)d_in[0];  // (8,128,56,56)
    const float* Wt   = (const float*)d_in[1];  // (64,128,5,5)
    const float* bias = (const float*)d_in[2];  // (64,)
    const float* Wlin = (const float*)d_in[3];  // (2,64)
    const float* blin = (const float*)d_in[4];  // (2,)
    float* out = (float*)d_out;                 // (8,56,56,2)

    prep_kernel<<<CP / 32, 512>>>(Wt, bias, Wlin, blin);   // 100 blocks
    proj_kernel<<<PIX / 256, 256>>>(x);                    // 98 blocks, exact
    final_kernel<<<(PIX + 127) / 128, 128>>>(out);         // 196 blocks
}

// round 13
// speedup vs baseline: 1.5687x; 1.0164x over previous
#include <cuda_runtime.h>
#include <math.h>

#define NB   8
#define C    128
#define H    56
#define W    56
#define O    64
#define NC   2
#define KS   5
#define P    25
#define P2   50           // NC * P
#define HW   (H * W)      // 3136
#define PIX  (NB * HW)    // 25088
#define CP   (C * P)      // 3200
#define CP4  (CP / 4)     // 800 float4 per o-row

typedef unsigned long long u64;

// Scratch (allocation-free rule: __device__ globals)
__device__ __align__(16) float g_V[P2 * C];  // folded weights V[k*P+p][c]
__device__ float g_const[NC];                // per-class constant
__device__ float g_Y[NB * P * HW * 2];       // Y[n][p][hw][{class0,class1}]

__device__ __forceinline__ void fma2(u64& d, u64 a, u64 b) {
    asm("fma.rn.f32x2 %0, %1, %2, %0;" : "+l"(d) : "l"(a), "l"(b));
}
__device__ __forceinline__ u64 pack2(float lo, float hi) {
    u64 r;
    asm("mov.b64 %0, {%1, %2};" : "=l"(r) : "f"(lo), "f"(hi));
    return r;
}
__device__ __forceinline__ float hadd2(u64 v) {
    float lo, hi;
    asm("mov.b64 {%0, %1}, %2;" : "=f"(lo), "=f"(hi) : "l"(v));
    return lo + hi;
}

// ---------------------------------------------------------------------------
// Kernel 1: V = Wlin(2x64) @ Wt(64x3200), float4 loads for MLP.
// 100 blocks x 128 threads. Thread (og, j4l): og=tid>>3 handles o in
// [4og,4og+4) for float4 column j4 = blk*8 + (tid&7). 4 independent
// LDG.128/thread; shared reduce over the 16 o-groups; 8 threads scatter out.
// ---------------------------------------------------------------------------
__global__ void __launch_bounds__(128) prep_kernel(const float* __restrict__ Wt,
                                                   const float* __restrict__ bias,
                                                   const float* __restrict__ Wlin,
                                                   const float* __restrict__ blin) {
    __shared__ float4 r0[16][8];
    __shared__ float4 r1[16][8];
    const float4* Wt4 = reinterpret_cast<const float4*>(Wt);

    int og  = threadIdx.x >> 3;          // 0..15
    int j4l = threadIdx.x & 7;           // 0..7
    int j4g = blockIdx.x * 8 + j4l;      // 0..799

    float4 s0 = make_float4(0.f, 0.f, 0.f, 0.f);
    float4 s1 = make_float4(0.f, 0.f, 0.f, 0.f);
    #pragma unroll
    for (int oo = 0; oo < 4; oo++) {
        int o = og * 4 + oo;
        float4 wv = Wt4[o * CP4 + j4g];  // LDG.128, 4 independent per thread
        float w0 = __ldg(&Wlin[o]);
        float w1 = __ldg(&Wlin[O + o]);
        s0.x = fmaf(w0, wv.x, s0.x); s0.y = fmaf(w0, wv.y, s0.y);
        s0.z = fmaf(w0, wv.z, s0.z); s0.w = fmaf(w0, wv.w, s0.w);
        s1.x = fmaf(w1, wv.x, s1.x); s1.y = fmaf(w1, wv.y, s1.y);
        s1.z = fmaf(w1, wv.z, s1.z); s1.w = fmaf(w1, wv.w, s1.w);
    }
    r0[og][j4l] = s0;
    r1[og][j4l] = s1;
    __syncthreads();

    if (threadIdx.x < 8) {
        float4 t0 = make_float4(0.f, 0.f, 0.f, 0.f);
        float4 t1 = make_float4(0.f, 0.f, 0.f, 0.f);
        #pragma unroll
        for (int g = 0; g < 16; g++) {
            float4 a = r0[g][threadIdx.x];
            float4 b = r1[g][threadIdx.x];
            t0.x += a.x; t0.y += a.y; t0.z += a.z; t0.w += a.w;
            t1.x += b.x; t1.y += b.y; t1.z += b.z; t1.w += b.w;
        }
        int jb = (blockIdx.x * 8 + threadIdx.x) * 4;
        const float* e0 = reinterpret_cast<const float*>(&t0);
        const float* e1 = reinterpret_cast<const float*>(&t1);
        #pragma unroll
        for (int e = 0; e < 4; e++) {
            int j = jb + e;
            int c = j / P, p = j % P;
            g_V[p * C + c]       = e0[e];   // class 0 rows
            g_V[(P + p) * C + c] = e1[e];   // class 1 rows
        }
    }

    if (blockIdx.x == 0 && threadIdx.x < NC) {
        float s = blin[threadIdx.x];
        #pragma unroll
        for (int o = 0; o < O; o++) s += bias[o] * Wlin[threadIdx.x * O + o];
        g_const[threadIdx.x] = s;
    }
}

// ---------------------------------------------------------------------------
// Kernel 2: projection. 392 blocks x 128 threads, 1 pixel/thread.
// Warps 0-1 = class 0, warps 2-3 = class 1 (weight LDG.128 warp-uniform,
// L1-resident; x LDGs 128B-coalesced). 25 f32x2 accumulators (~100 regs)
// -> up to 4 co-resident blocks/SM for latency hiding; all 148 SMs active,
// worst-case tail 3 blocks = 192 px/SM (vs R12: 98 blocks, 50 SMs idle).
// ---------------------------------------------------------------------------
__global__ void __launch_bounds__(128, 4) proj_kernel(const float* __restrict__ x) {
    int tid  = threadIdx.x;
    int k    = tid >> 6;                  // class per warp-pair
    int lane = tid & 63;
    int pix  = blockIdx.x * 64 + lane;    // 392*64 = 25088, exact

    int n  = pix / HW;
    int hw = pix % HW;
    const float* xb = x + (size_t)n * C * HW + hw;

    const ulonglong2* __restrict__ Vk =
        reinterpret_cast<const ulonglong2*>(g_V) + (size_t)k * P * (C / 4);

    u64 acc[P];
    #pragma unroll
    for (int p = 0; p < P; p++) acc[p] = 0ull;

    #pragma unroll 4
    for (int c4 = 0; c4 < C / 4; c4++) {
        float x0 = xb[(c4 * 4 + 0) * HW];
        float x1 = xb[(c4 * 4 + 1) * HW];
        float x2 = xb[(c4 * 4 + 2) * HW];
        float x3 = xb[(c4 * 4 + 3) * HW];
        u64 xp01 = pack2(x0, x1);
        u64 xp23 = pack2(x2, x3);
        #pragma unroll
        for (int p = 0; p < P; p++) {
            ulonglong2 wv = Vk[p * (C / 4) + c4];   // uniform LDG.128, L1-hit
            fma2(acc[p], wv.x, xp01);
            fma2(acc[p], wv.y, xp23);
        }
    }

    // Y[n][p][hw][k]
    float* yb = g_Y + ((size_t)n * P * HW + hw) * 2 + k;
    #pragma unroll
    for (int p = 0; p < P; p++)
        yb[(size_t)p * HW * 2] = hadd2(acc[p]);
}

// ---------------------------------------------------------------------------
// Kernel 3: 5x5 gather + drift/exp epilogue. Thread = (pixel, class):
// 2x warps vs pixel-per-thread; loads stay 128B-coalesced (lane parity =
// class = consecutive 4B). Fast-math intrinsics (tolerance 1e-3 >> err).
// ---------------------------------------------------------------------------
__global__ void __launch_bounds__(128) final_kernel(float* __restrict__ out) {
    int t   = blockIdx.x * 128 + threadIdx.x;   // 392*128 = 50176, exact
    int pix = t >> 1;
    int k   = t & 1;
    int n  = pix / HW;
    int hw = pix % HW;
    int h  = hw / W;
    int w  = hw % W;

    const float* yb = g_Y + ((size_t)n * P * HW) * 2 + k;
    float ck = g_const[k];

    float sum = 0.f, as = 0.f, ys = 0.f, xs = 0.f;

    #pragma unroll
    for (int i = 0; i < KS; i++) {
        int hh = h + i - 2;
        bool hin = (hh >= 0) && (hh < H);
        #pragma unroll
        for (int j = 0; j < KS; j++) {
            int ww = w + j - 2;
            bool in = hin && (ww >= 0) && (ww < W);
            int p = i * KS + j;
            float v = in ? yb[((size_t)p * HW + hh * W + ww) * 2] : 0.f;
            float m = v + ck;
            float a = fabsf(m);
            sum += m;
            as  += a;
            ys  = fmaf(a, (float)(i - 2), ys);
            xs  = fmaf(a, (float)(j - 2), xs);
        }
    }

    float yd = __fdividef(ys, as);
    float xd = __fdividef(xs, as);
    float d  = sqrtf(fmaf(xd, xd, yd * yd));
    out[pix * 2 + k] = sum * __expf(-0.5f * d);
}

// ---------------------------------------------------------------------------
extern "C" void kernel_launch(void* const* d_in, const int* in_sizes, int n_in,
                              void* d_out, int out_size) {
    const float* x    = (const float*)d_in[0];  // (8,128,56,56)
    const float* Wt   = (const float*)d_in[1];  // (64,128,5,5)
    const float* bias = (const float*)d_in[2];  // (64,)
    const float* Wlin = (const float*)d_in[3];  // (2,64)
    const float* blin = (const float*)d_in[4];  // (2,)
    float* out = (float*)d_out;                 // (8,56,56,2)

    prep_kernel<<<100, 128>>>(Wt, bias, Wlin, blin);   // 100 blocks
    proj_kernel<<<392, 128>>>(x);                      // all SMs, fine tail
    final_kernel<<<392, 128>>>(out);                   // (pixel, class) split
}